// round 5
// baseline (speedup 1.0000x reference)
#include <cuda_runtime.h>
#include <cuda_fp16.h>

#define N_GENES 20000
#define UNITS   10000
#define DEG     32
#define BATCH   128

// |feature| transposed to [gene][batch] in fp16: 5.12 MB, L2-resident.
// Row = 256B; each (unit, deg) gather reads one full row, coalesced.
__device__ __half g_featT[(size_t)N_GENES * BATCH];

// ---------------------------------------------------------------------------
// K1: tiled transpose + fabs + fp16.  feature [128, 20000] -> featT [N, B]
// ---------------------------------------------------------------------------
__global__ void transpose_abs_kernel(const float* __restrict__ feature) {
    __shared__ float tile[32][33];               // tile[batch][gene]
    const int gx = blockIdx.x * 32;
    const int bx = blockIdx.y * 32;
    const int tx = threadIdx.x, ty = threadIdx.y;

#pragma unroll
    for (int k = 0; k < 32; k += 8)
        tile[ty + k][tx] = fabsf(feature[(size_t)(bx + ty + k) * N_GENES + (gx + tx)]);
    __syncthreads();

    const int t = ty * 32 + tx;
#pragma unroll
    for (int iter = 0; iter < 2; iter++) {
        const int tt  = iter * 256 + t;
        const int g_l = tt >> 4;                 // 0..31
        const int p   = tt & 15;                 // batch pair
        const __half2 h = __floats2half2_rn(tile[2 * p][g_l], tile[2 * p + 1][g_l]);
        *(__half2*)&g_featT[(size_t)(gx + g_l) * BATCH + bx + 2 * p] = h;
    }
}

// ---------------------------------------------------------------------------
// K2: gather-sum. One warp per unit. Per iteration the warp loads TWO gene
// rows with one LDG.128: lanes 0-15 cover gene 2it (16B batch slice each),
// lanes 16-31 cover gene 2it+1. Offsets broadcast by one SHFL.IDX with a
// lane-dependent source. Batches of 4 LDG.128 kept in flight for MLP.
// fp16 accumulate, fp32 flush every 8 genes; cross-half combine via
// shfl_xor(16); coalesced smem-staged output.
// ---------------------------------------------------------------------------
__global__ void __launch_bounds__(256, 5) ppi_gather_kernel(
    const int*   __restrict__ ppi,     // int32 (JAX x64-disabled)
    const float* __restrict__ kern,
    const float* __restrict__ bias,
    float*       __restrict__ out)
{
    __shared__ float tile[8][BATCH + 4];

    const int lane   = threadIdx.x & 31;
    const int hlane  = lane & 15;                 // batch-slice owner (16B)
    const int hsel   = lane >> 4;                 // 0: even gene, 1: odd gene
    const int warp   = threadIdx.x >> 5;
    const int u_base = blockIdx.x * 8;
    const int u      = u_base + warp;

    // Row byte-offset of ppi[u][lane] (row = 256B), coalesced 128B load.
    const int myoff = ppi[(size_t)u * DEG + lane] << 8;
    const char* base = (const char*)g_featT + hlane * 16;

    float facc[8];
#pragma unroll
    for (int j = 0; j < 8; j++) facc[j] = 0.f;

#pragma unroll
    for (int half = 0; half < 2; half++) {        // 2 flush periods x 16 genes
        __half2 hacc[4];
#pragma unroll
        for (int j = 0; j < 4; j++) hacc[j] = __floats2half2_rn(0.f, 0.f);

#pragma unroll
        for (int bb = 0; bb < 2; bb++) {          // 2 batches of 4 LDG.128
            uint4 raw[4];
#pragma unroll
            for (int q = 0; q < 4; q++) {
                const int it  = half * 8 + bb * 4 + q;          // 0..15
                const int off = __shfl_sync(0xffffffffu, myoff, 2 * it + hsel);
                raw[q] = *(const uint4*)(base + off);
            }
#pragma unroll
            for (int q = 0; q < 4; q++) {
                hacc[0] = __hadd2(hacc[0], *(const __half2*)&raw[q].x);
                hacc[1] = __hadd2(hacc[1], *(const __half2*)&raw[q].y);
                hacc[2] = __hadd2(hacc[2], *(const __half2*)&raw[q].z);
                hacc[3] = __hadd2(hacc[3], *(const __half2*)&raw[q].w);
            }
        }
#pragma unroll
        for (int j = 0; j < 4; j++) {             // fp32 flush
            const float2 f = __half22float2(hacc[j]);
            facc[2 * j]     += f.x;
            facc[2 * j + 1] += f.y;
        }
    }

    // Combine the two half-warps (same batch slice, disjoint gene subsets).
#pragma unroll
    for (int j = 0; j < 8; j++)
        facc[j] += __shfl_xor_sync(0xffffffffu, facc[j], 16);

    const float kv = kern[u];
    const float bv = bias[u];
    float r[8];
#pragma unroll
    for (int j = 0; j < 8; j++)
        r[j] = tanhf(fmaf(facc[j], kv, bv));

    if (lane < 16) {                              // conflict-free 512B row
        *(float4*)&tile[warp][hlane * 8]     = make_float4(r[0], r[1], r[2], r[3]);
        *(float4*)&tile[warp][hlane * 8 + 4] = make_float4(r[4], r[5], r[6], r[7]);
    }
    __syncthreads();

    // Coalesced output: 8-thread groups write contiguous 32B chunks per row.
    for (int t = threadIdx.x; t < BATCH * 8; t += 256) {
        const int u_l = t & 7;
        const int b   = t >> 3;
        out[(size_t)b * UNITS + (u_base + u_l)] = tile[u_l][b];
    }
}

// ---------------------------------------------------------------------------
extern "C" void kernel_launch(void* const* d_in, const int* in_sizes, int n_in,
                              void* d_out, int out_size) {
    const float* feature = (const float*)d_in[0];
    const int*   ppi     = (const int*)d_in[1];
    const float* kern    = (const float*)d_in[2];
    const float* bias    = (const float*)d_in[3];
    float*       out     = (float*)d_out;

    dim3 tgrid(N_GENES / 32, BATCH / 32);   // (625, 4)
    dim3 tblock(32, 8);
    transpose_abs_kernel<<<tgrid, tblock>>>(feature);

    ppi_gather_kernel<<<UNITS / 8, 256>>>(ppi, kern, bias, out);  // 1250 CTAs
}

// round 6
// speedup vs baseline: 1.0021x; 1.0021x over previous
#include <cuda_runtime.h>
#include <cuda_fp16.h>

#define N_GENES 20000
#define UNITS   10000
#define DEG     32
#define BATCH   128

// |feature| transposed to [gene][batch] in fp16: 5.12 MB, L2-resident.
// Row = 256B; each (unit, deg) gather reads one full row, coalesced.
__device__ __half g_featT[(size_t)N_GENES * BATCH];

// ---------------------------------------------------------------------------
// K1: tiled transpose + fabs + fp16.  feature [128, 20000] -> featT [N, B]
// ---------------------------------------------------------------------------
__global__ void transpose_abs_kernel(const float* __restrict__ feature) {
    __shared__ float tile[32][33];               // tile[batch][gene]
    const int gx = blockIdx.x * 32;
    const int bx = blockIdx.y * 32;
    const int tx = threadIdx.x, ty = threadIdx.y;

#pragma unroll
    for (int k = 0; k < 32; k += 8)
        tile[ty + k][tx] = fabsf(feature[(size_t)(bx + ty + k) * N_GENES + (gx + tx)]);
    __syncthreads();

    const int t = ty * 32 + tx;
#pragma unroll
    for (int iter = 0; iter < 2; iter++) {
        const int tt  = iter * 256 + t;
        const int g_l = tt >> 4;                 // 0..31
        const int p   = tt & 15;                 // batch pair
        const __half2 h = __floats2half2_rn(tile[2 * p][g_l], tile[2 * p + 1][g_l]);
        *(__half2*)&g_featT[(size_t)(gx + g_l) * BATCH + bx + 2 * p] = h;
    }
}

// ---------------------------------------------------------------------------
// K2: gather-sum, split-degree. TWO warps per unit: warp parity h sums genes
// [16h, 16h+16). Within a warp, each LDG.128 covers two gene rows (half-warp
// per gene, 16B batch slice per lane); 4 loads batched in flight. Partials
// combined in smem; fma+tanh+store in the epilogue (coalesced 32B chunks).
// ---------------------------------------------------------------------------
__global__ void __launch_bounds__(512, 3) ppi_gather_kernel(
    const int*   __restrict__ ppi,     // int32 (JAX x64-disabled)
    const float* __restrict__ kern,
    const float* __restrict__ bias,
    float*       __restrict__ out)
{
    __shared__ float partial[8][2][BATCH + 4];

    const int lane   = threadIdx.x & 31;
    const int hlane  = lane & 15;                 // batch-slice owner (16B)
    const int hsel   = lane >> 4;                 // 0: even gene, 1: odd gene
    const int warp   = threadIdx.x >> 5;          // 0..15
    const int pair   = warp >> 1;                 // unit slot 0..7
    const int h      = warp & 1;                  // gene half
    const int u_base = blockIdx.x * 8;
    const int u      = u_base + pair;

    // Lanes 0-15 hold offsets of this warp's 16 genes (lanes 16-31 duplicate).
    const int myoff = ppi[(size_t)u * DEG + h * 16 + hlane] << 8;
    const char* base = (const char*)g_featT + hlane * 16;

    __half2 hacc[4];
#pragma unroll
    for (int j = 0; j < 4; j++) hacc[j] = __floats2half2_rn(0.f, 0.f);

#pragma unroll
    for (int bb = 0; bb < 2; bb++) {              // 2 batches of 4 LDG.128
        uint4 raw[4];
#pragma unroll
        for (int q = 0; q < 4; q++) {
            const int it  = bb * 4 + q;           // 0..7
            const int off = __shfl_sync(0xffffffffu, myoff, 2 * it + hsel);
            raw[q] = *(const uint4*)(base + off);
        }
#pragma unroll
        for (int q = 0; q < 4; q++) {
            hacc[0] = __hadd2(hacc[0], *(const __half2*)&raw[q].x);
            hacc[1] = __hadd2(hacc[1], *(const __half2*)&raw[q].y);
            hacc[2] = __hadd2(hacc[2], *(const __half2*)&raw[q].z);
            hacc[3] = __hadd2(hacc[3], *(const __half2*)&raw[q].w);
        }
    }

    // fp32 flush (8 genes per hacc lane-slot) + cross-half combine -> 16 genes
    float facc[8];
#pragma unroll
    for (int j = 0; j < 4; j++) {
        const float2 f = __half22float2(hacc[j]);
        facc[2 * j]     = f.x;
        facc[2 * j + 1] = f.y;
    }
#pragma unroll
    for (int j = 0; j < 8; j++)
        facc[j] += __shfl_xor_sync(0xffffffffu, facc[j], 16);

    if (lane < 16) {                              // conflict-free 512B row
        *(float4*)&partial[pair][h][hlane * 8]     = make_float4(facc[0], facc[1], facc[2], facc[3]);
        *(float4*)&partial[pair][h][hlane * 8 + 4] = make_float4(facc[4], facc[5], facc[6], facc[7]);
    }
    __syncthreads();

    // Epilogue: sum the two halves, fma+tanh, coalesced 32B-chunk stores.
    for (int t = threadIdx.x; t < BATCH * 8; t += 512) {
        const int u_l = t & 7;
        const int b   = t >> 3;
        const int uu  = u_base + u_l;
        const float s = partial[u_l][0][b] + partial[u_l][1][b];
        out[(size_t)b * UNITS + uu] = tanhf(fmaf(s, kern[uu], bias[uu]));
    }
}

// ---------------------------------------------------------------------------
extern "C" void kernel_launch(void* const* d_in, const int* in_sizes, int n_in,
                              void* d_out, int out_size) {
    const float* feature = (const float*)d_in[0];
    const int*   ppi     = (const int*)d_in[1];
    const float* kern    = (const float*)d_in[2];
    const float* bias    = (const float*)d_in[3];
    float*       out     = (float*)d_out;

    dim3 tgrid(N_GENES / 32, BATCH / 32);   // (625, 4)
    dim3 tblock(32, 8);
    transpose_abs_kernel<<<tgrid, tblock>>>(feature);

    ppi_gather_kernel<<<UNITS / 8, 512>>>(ppi, kern, bias, out);  // 1250 CTAs
}